// round 9
// baseline (speedup 1.0000x reference)
#include <cuda_runtime.h>
#include <cuda_fp16.h>
#include <math.h>
#include <stdint.h>

// B=4,H=16 -> BH=64; S=1024; D=64; rel-pos P=32
#define BH   64
#define SEQ  1024
#define DH   64
#define NTHR 256
#define NROW 64
#define ISD  0.125f
#define NEGINF (-INFINITY)

#define KW_STRW 36      // K fp16 tile stride (words)
#define VT_STRW 68      // V^T fp16 tile stride (words)
#define QSTG_STR 68     // fp32 Q staging stride (floats, 16B-divisible)
#define KBUF_B 18432    // 128*36*4
#define VBUF_B 17408    // 64*68*4

// smem layout (bytes)
#define OFF_KW   0                       // K bufs [2][128][36w]  36864  (preamble: Q fp32 [64][68]; tail: O exchange)
#define OFF_VT   36864                   // V^T bufs [2][64][68w] 34816  (preamble: pe_k [33][66] f32)
#define OFF_QPE  71680                   // qpe [64][34] f32       8704  (tail: l/w0/inv scratch)
#define OFF_W    80384                   // taps [64][34] f32      8704
#define OFF_PEV  89088                   // pe_v [33][66] f32      8712
#define OFF_M    97800                   // M bound [64]            256
#define SMEM_TOTAL 98056

__device__ __align__(16) __half g_Kh[(size_t)BH * SEQ * DH];
__device__ __align__(16) __half g_Vth[(size_t)BH * DH * SEQ];   // [bh][d][k]
__device__ float g_maxk[BH];

static __device__ __forceinline__ uint32_t h2u(float a, float b) {
    __half2 h = __floats2half2_rn(a, b);
    return *reinterpret_cast<uint32_t*>(&h);
}
static __device__ __forceinline__ void mma16(float* d, const uint32_t* a,
                                             uint32_t b0, uint32_t b1) {
    asm volatile("mma.sync.aligned.m16n8k16.row.col.f32.f16.f16.f32 "
        "{%0,%1,%2,%3},{%4,%5,%6,%7},{%8,%9},{%0,%1,%2,%3};"
        : "+f"(d[0]), "+f"(d[1]), "+f"(d[2]), "+f"(d[3])
        : "r"(a[0]), "r"(a[1]), "r"(a[2]), "r"(a[3]), "r"(b0), "r"(b1));
}
static __device__ __forceinline__ uint32_t smem_u32(const void* p) {
    uint32_t a;
    asm("{ .reg .u64 t; cvta.to.shared.u64 t, %1; cvt.u32.u64 %0, t; }" : "=r"(a) : "l"(p));
    return a;
}
static __device__ __forceinline__ void cpa16(uint32_t dst, const void* src) {
    asm volatile("cp.async.cg.shared.global [%0], [%1], 16;" :: "r"(dst), "l"(src));
}
#define CP_COMMIT() asm volatile("cp.async.commit_group;" ::: "memory")
#define CP_WAIT0()  asm volatile("cp.async.wait_group 0;" ::: "memory")

// ---- pre-pass: K -> fp16, V -> fp16 transposed ----
__global__ __launch_bounds__(256)
void convert_kernel(const float* __restrict__ K, const float* __restrict__ V)
{
    __shared__ float ts[128][65];
    const int bh = blockIdx.x, kt = blockIdx.y, tid = threadIdx.x;
    const size_t base = (size_t)bh * SEQ * DH + (size_t)kt * 128 * DH;
    // K elementwise
    const float4* Ks = (const float4*)(K + base);
    uint2* Kd = (uint2*)(g_Kh + base);
    #pragma unroll
    for (int n = 0; n < 8; n++) {
        int i = tid + n * 256;
        float4 v = Ks[i];
        uint2 u; u.x = h2u(v.x, v.y); u.y = h2u(v.z, v.w);
        Kd[i] = u;
    }
    // V transpose via smem
    #pragma unroll
    for (int n = 0; n < 8; n++) {
        int i = tid + n * 256;
        int r = i >> 4, c = (i & 15) * 4;
        float4 v = *(const float4*)(V + base + r * DH + c);
        ts[r][c] = v.x; ts[r][c+1] = v.y; ts[r][c+2] = v.z; ts[r][c+3] = v.w;
    }
    __syncthreads();
    __half* Vh = g_Vth + (size_t)bh * SEQ * DH + (size_t)kt * 128;
    #pragma unroll
    for (int n = 0; n < 4; n++) {
        int i = tid + n * 256;
        int d = i >> 4, c8 = (i & 15) * 8;
        __half hv[8];
        #pragma unroll
        for (int j = 0; j < 8; j++) hv[j] = __float2half_rn(ts[c8 + j][d]);
        *(uint4*)(Vh + (size_t)d * SEQ + c8) = *(uint4*)hv;
    }
}

// ---- precompute: per-bh max ||k_row|| ----
__global__ __launch_bounds__(256, 4)
void knorm_kernel(const float* __restrict__ K)
{
    __shared__ float red[8];
    const int bh = blockIdx.x, tid = threadIdx.x;
    const float* Kb = K + (size_t)bh * SEQ * DH;
    float mx = 0.f;
    for (int r = tid; r < SEQ; r += 256) {
        const float4* kr = (const float4*)(Kb + (size_t)r * DH);
        float s = 0.f;
        #pragma unroll
        for (int i = 0; i < 16; i++) {
            float4 v = kr[i];
            s += v.x*v.x + v.y*v.y + v.z*v.z + v.w*v.w;
        }
        mx = fmaxf(mx, s);
    }
    #pragma unroll
    for (int o = 16; o > 0; o >>= 1) mx = fmaxf(mx, __shfl_xor_sync(0xffffffffu, mx, o));
    if ((tid & 31) == 0) red[tid >> 5] = mx;
    __syncthreads();
    if (tid == 0) {
        float m = red[0];
        #pragma unroll
        for (int i = 1; i < 8; i++) m = fmaxf(m, red[i]);
        g_maxk[bh] = sqrtf(m);
    }
}

__global__ __launch_bounds__(NTHR, 2)
void relattn_mma(const float* __restrict__ Q, const float* __restrict__ PEK,
                 const float* __restrict__ PEV,
                 float* __restrict__ Out, float* __restrict__ Pout)
{
    extern __shared__ char sm8[];
    const uint32_t sbase = smem_u32(sm8);
    float*    qstg= (float*)(sm8 + OFF_KW);      // preamble overlay
    float*    sPEK= (float*)(sm8 + OFF_VT);      // preamble overlay
    float*    sQPE= (float*)(sm8 + OFF_QPE);
    float*    sW  = (float*)(sm8 + OFF_W);
    float*    sPEV= (float*)(sm8 + OFF_PEV);
    float*    sM  = (float*)(sm8 + OFF_M);
    float*    sLR = (float*)(sm8 + OFF_QPE);           // tail scratch
    float*    sWR = (float*)(sm8 + OFF_QPE) + 128;
    float*    sINV= (float*)(sm8 + OFF_QPE) + 256;
    float*    sOX = (float*)(sm8 + OFF_KW);            // tail O-exchange [2][4wm][16][36]

    const int tid = threadIdx.x, lane = tid & 31, warp = tid >> 5;
    const int g = lane >> 2, tg = lane & 3;
    const int wm = warp & 3, wn = warp >> 2;           // 4 x 2 warp grid
    const int rm = wm * 16, cn = wn * 64, dn = wn * 32;

    const int bx = blockIdx.x;
    const int qblk = 15 - (bx >> 6);                   // longest first
    const int bh = bx & 63;
    const int q0 = qblk * NROW;
    const int ntiles = (q0 + NROW + 127) >> 7;

    const float* Qb = Q + (size_t)bh * SEQ * DH;
    const __half* Khb = g_Kh + (size_t)bh * SEQ * DH;
    const __half* Vthb = g_Vth + (size_t)bh * SEQ * DH;
    const float maxk = g_maxk[bh];

    // ---- prologue: async-stage tile 0 into buffer 1 (buffers: bsel(kt) = (kt+1)&1) ----
    {
        const __half* ksrc = Khb;
        const __half* vsrc = Vthb;
        uint32_t kdst = sbase + OFF_KW + 1 * KBUF_B;
        uint32_t vdst = sbase + OFF_VT + 1 * VBUF_B;
        #pragma unroll
        for (int n = 0; n < 4; n++) {
            int i = tid + n * NTHR;
            int r = i >> 3, c4 = i & 7;
            cpa16(kdst + (uint32_t)(r * KW_STRW + c4 * 4) * 4u, ksrc + r * DH + c4 * 8);
        }
        #pragma unroll
        for (int n = 0; n < 4; n++) {
            int i = tid + n * NTHR;
            int d = i >> 4, c4 = i & 15;
            cpa16(vdst + (uint32_t)(d * VT_STRW + c4 * 4) * 4u, vsrc + (size_t)d * SEQ + c4 * 8);
        }
        CP_COMMIT();
    }

    // ---- preamble: stage Q fp32 + pe tables; zero taps ----
    #pragma unroll
    for (int n = 0; n < 4; n++) {
        int i = tid + n * NTHR;
        int r = i >> 4, c = (i & 15) * 4;
        *(float4*)(qstg + r * QSTG_STR + c) =
            *(const float4*)(Qb + (size_t)(q0 + r) * DH + c);
    }
    for (int i = tid; i < 33 * 16; i += NTHR) {
        int r = i >> 4, c = (i & 15) * 4;
        float4 a = *(const float4*)(PEK + r * DH + c);
        sPEK[r*66+c] = a.x; sPEK[r*66+c+1] = a.y; sPEK[r*66+c+2] = a.z; sPEK[r*66+c+3] = a.w;
        float4 b = *(const float4*)(PEV + r * DH + c);
        sPEV[r*66+c] = b.x; sPEV[r*66+c+1] = b.y; sPEV[r*66+c+2] = b.z; sPEV[r*66+c+3] = b.w;
    }
    for (int i = tid; i < NROW * 34; i += NTHR) sW[i] = 0.f;
    __syncthreads();

    // ---- qpe[row][j] = q_row . pe_k[j] ----
    {
        int row = tid >> 2, quarter = tid & 3;
        const float* qr = qstg + row * QSTG_STR;
        int j0 = quarter * 8, jn = (quarter == 3) ? 9 : 8;
        #pragma unroll 1
        for (int jj = 0; jj < jn; jj++) {
            int j = j0 + jj;
            const float* pk = sPEK + j * 66;
            float a = 0.f;
            #pragma unroll
            for (int d = 0; d < 64; d++) a = fmaf(qr[d], pk[d], a);
            sQPE[row * 34 + j] = a;
        }
    }
    __syncthreads();

    // ---- M bound per row; Q fragments resident ----
    if (tid < NROW) {
        const float* qr = qstg + tid * QSTG_STR;
        float qn = 0.f;
        #pragma unroll
        for (int d = 0; d < 64; d++) qn = fmaf(qr[d], qr[d], qn);
        float mb = sQPE[tid * 34];
        #pragma unroll
        for (int j = 1; j < 33; j++) mb = fmaxf(mb, sQPE[tid * 34 + j]);
        sM[tid] = sqrtf(qn) * maxk + mb;
    }
    uint32_t qa[4][4];
    #pragma unroll
    for (int ks = 0; ks < 4; ks++) {
        const float* r0 = qstg + (rm + g) * QSTG_STR + 16*ks + 2*tg;
        const float* r1 = qstg + (rm + 8 + g) * QSTG_STR + 16*ks + 2*tg;
        qa[ks][0] = h2u(r0[0], r0[1]);
        qa[ks][1] = h2u(r1[0], r1[1]);
        qa[ks][2] = h2u(r0[8], r0[9]);
        qa[ks][3] = h2u(r1[8], r1[9]);
    }
    __syncthreads();

    float Mrow[2];
    #pragma unroll
    for (int s = 0; s < 2; s++) Mrow[s] = sM[rm + 8*s + g];

    // ================= main loop: 1 barrier per tile =================
    float lloc[2] = {0.f, 0.f};
    float w0[2]   = {0.f, 0.f};
    float o[8][4] = {};

    for (int kt = 0; kt < ntiles; kt++) {
        const int bsel = (kt + 1) & 1;
        CP_WAIT0();
        __syncthreads();     // tile kt staged + all warps done with buffer bsel^1

        if (kt + 1 < ntiles) {
            const __half* ksrc = Khb + (size_t)(kt + 1) * 128 * DH;
            const __half* vsrc = Vthb + (size_t)(kt + 1) * 128;
            uint32_t kdst = sbase + OFF_KW + (bsel ^ 1) * KBUF_B;
            uint32_t vdst = sbase + OFF_VT + (bsel ^ 1) * VBUF_B;
            #pragma unroll
            for (int n = 0; n < 4; n++) {
                int i = tid + n * NTHR;
                int r = i >> 3, c4 = i & 7;
                cpa16(kdst + (uint32_t)(r * KW_STRW + c4 * 4) * 4u, ksrc + r * DH + c4 * 8);
            }
            #pragma unroll
            for (int n = 0; n < 4; n++) {
                int i = tid + n * NTHR;
                int d = i >> 4, c4 = i & 15;
                cpa16(vdst + (uint32_t)(d * VT_STRW + c4 * 4) * 4u, vsrc + (size_t)d * SEQ + c4 * 8);
            }
            CP_COMMIT();
        }

        const uint32_t* kwb = (const uint32_t*)(sm8 + OFF_KW + bsel * KBUF_B);
        const uint32_t* vwb = (const uint32_t*)(sm8 + OFF_VT + bsel * VBUF_B);
        const bool live = (kt*128 + cn) <= (q0 + rm + 15);

        if (live) {
            // ---- score: 16 rows x 64 cols ----
            float acc[8][4] = {};
            #pragma unroll
            for (int ks = 0; ks < 4; ks++)
                #pragma unroll
                for (int nt = 0; nt < 8; nt++) {
                    int bb = (cn + 8*nt + g) * KW_STRW + 8*ks + tg;
                    mma16(acc[nt], qa[ks], kwb[bb], kwb[bb + 4]);
                }

            // ---- bias + mask + e; emit e to gmem; pack PV A-frags in regs ----
            uint32_t pa[4][4];
            #pragma unroll
            for (int nt = 0; nt < 8; nt++) {
                float p[4];
                #pragma unroll
                for (int c = 0; c < 4; c++) {
                    int s = c >> 1;
                    int row = rm + 8*s + g;
                    int col = kt*128 + cn + 8*nt + 2*tg + (c&1);
                    int qg = q0 + row;
                    float v = NEGINF;
                    if (col <= qg) {
                        int j = col - qg + 32; j = j < 0 ? 0 : j;
                        v = acc[nt][c] + sQPE[row*34 + j];
                    }
                    float e = __expf((v - Mrow[s]) * ISD);
                    p[c] = e;
                    lloc[s] += e;
                    if (col <= qg - 32) w0[s] += e;
                    else if (col <= qg) sW[row*34 + (col - qg + 32)] = e;
                }
                int rowL = rm + g, rowH = rm + 8 + g;
                int colb = kt*128 + cn + 8*nt + 2*tg;
                *(float2*)(Pout + ((size_t)bh*SEQ + q0 + rowL)*SEQ + colb) = make_float2(p[0], p[1]);
                *(float2*)(Pout + ((size_t)bh*SEQ + q0 + rowH)*SEQ + colb) = make_float2(p[2], p[3]);
                int ki = nt >> 1;
                if ((nt & 1) == 0) { pa[ki][0] = h2u(p[0], p[1]); pa[ki][1] = h2u(p[2], p[3]); }
                else               { pa[ki][2] = h2u(p[0], p[1]); pa[ki][3] = h2u(p[2], p[3]); }
            }

            // ---- PV from registers: O[16 rows][64 d] over this warp's 64 keys ----
            #pragma unroll
            for (int ks = 0; ks < 4; ks++) {
                if (kt*128 + cn + 16*ks <= q0 + rm + 15) {
                    #pragma unroll
                    for (int nt = 0; nt < 8; nt++) {
                        int bb = (8*nt + g) * VT_STRW + (cn >> 1) + 8*ks + tg;
                        mma16(o[nt], pa[ks], vwb[bb], vwb[bb + 4]);
                    }
                }
            }
        } else {
            #pragma unroll
            for (int nt = 0; nt < 8; nt++) {
                int rowL = rm + g, rowH = rm + 8 + g;
                int colb = kt*128 + cn + 8*nt + 2*tg;
                *(float2*)(Pout + ((size_t)bh*SEQ + q0 + rowL)*SEQ + colb) = make_float2(0.f, 0.f);
                *(float2*)(Pout + ((size_t)bh*SEQ + q0 + rowH)*SEQ + colb) = make_float2(0.f, 0.f);
            }
        }
    }
    __syncthreads();   // staging buffers dead; overlays safe

    // ---- l / w0 reduce + O-exchange store ----
    #pragma unroll
    for (int s = 0; s < 2; s++) {
        lloc[s] += __shfl_xor_sync(0xffffffffu, lloc[s], 1);
        lloc[s] += __shfl_xor_sync(0xffffffffu, lloc[s], 2);
        w0[s]   += __shfl_xor_sync(0xffffffffu, w0[s], 1);
        w0[s]   += __shfl_xor_sync(0xffffffffu, w0[s], 2);
    }
    if (tg == 0)
        #pragma unroll
        for (int s = 0; s < 2; s++) {
            int row = rm + 8*s + g;
            sLR[row*2 + wn] = lloc[s];
            sWR[row*2 + wn] = w0[s];
        }
    {   // store the d-half this warp does NOT keep
        float* dst = sOX + wn*2304 + wm*576;
        #pragma unroll
        for (int j = 0; j < 4; j++) {
            int nt = 4*(1 - wn) + j;
            dst[g*36 + 8*j + 2*tg]         = o[nt][0];
            dst[g*36 + 8*j + 2*tg + 1]     = o[nt][1];
            dst[(g+8)*36 + 8*j + 2*tg]     = o[nt][2];
            dst[(g+8)*36 + 8*j + 2*tg + 1] = o[nt][3];
        }
    }
    __syncthreads();

    float oo[4][4];
    {   // add partner's contribution for the kept half
        const float* src = sOX + (1 - wn)*2304 + wm*576;
        #pragma unroll
        for (int j = 0; j < 4; j++) {
            int nt = 4*wn + j;
            oo[j][0] = o[nt][0] + src[g*36 + 8*j + 2*tg];
            oo[j][1] = o[nt][1] + src[g*36 + 8*j + 2*tg + 1];
            oo[j][2] = o[nt][2] + src[(g+8)*36 + 8*j + 2*tg];
            oo[j][3] = o[nt][3] + src[(g+8)*36 + 8*j + 2*tg + 1];
        }
    }
    float invl[2], w0f[2];
    #pragma unroll
    for (int s = 0; s < 2; s++) {
        int row = rm + 8*s + g;
        invl[s] = 1.f / (sLR[row*2] + sLR[row*2+1]);
        w0f[s]  = (sWR[row*2] + sWR[row*2+1]) * invl[s];
    }
    if (tg == 0 && wn == 0)
        #pragma unroll
        for (int s = 0; s < 2; s++) sINV[rm + 8*s + g] = invl[s];

    #pragma unroll
    for (int nt = 0; nt < 4; nt++)
        #pragma unroll
        for (int c = 0; c < 4; c++)
            oo[nt][c] *= invl[c>>1];

    // ---- rel-pos value epilogue ----
    #pragma unroll 1
    for (int j = 0; j <= 32; j++) {
        float wj[2];
        #pragma unroll
        for (int s = 0; s < 2; s++) {
            int row = rm + 8*s + g;
            wj[s] = (j == 0) ? w0f[s] : sW[row*34 + j] * invl[s];
        }
        #pragma unroll
        for (int nt = 0; nt < 4; nt++) {
            float pe0 = sPEV[j*66 + dn + 8*nt + 2*tg];
            float pe1 = sPEV[j*66 + dn + 8*nt + 2*tg + 1];
            oo[nt][0] = fmaf(wj[0], pe0, oo[nt][0]);
            oo[nt][1] = fmaf(wj[0], pe1, oo[nt][1]);
            oo[nt][2] = fmaf(wj[1], pe0, oo[nt][2]);
            oo[nt][3] = fmaf(wj[1], pe1, oo[nt][3]);
        }
    }

    // ---- write output ----
    #pragma unroll
    for (int nt = 0; nt < 4; nt++) {
        int rowL = rm + g, rowH = rm + 8 + g;
        int colb = dn + 8*nt + 2*tg;
        *(float2*)(Out + ((size_t)bh*SEQ + q0 + rowL)*DH + colb) = make_float2(oo[nt][0], oo[nt][1]);
        *(float2*)(Out + ((size_t)bh*SEQ + q0 + rowH)*DH + colb) = make_float2(oo[nt][2], oo[nt][3]);
    }

    __syncthreads();   // sINV + e-writes visible

    // ---- in-place rescale of Pout (e -> p = e/l), L2-hot ----
    {
        const int cols = ntiles * 128;
        for (int r = warp; r < NROW; r += 8) {
            float inv = sINV[r];
            float4* rowp = (float4*)(Pout + ((size_t)bh*SEQ + q0 + r)*SEQ);
            for (int c4 = lane; c4 < (cols >> 2); c4 += 32) {
                float4 v = rowp[c4];
                v.x *= inv; v.y *= inv; v.z *= inv; v.w *= inv;
                rowp[c4] = v;
            }
        }
    }

    // ---- zero-fill masked p region ----
    int zc = SEQ - ntiles * 128;
    if (zc > 0) {
        int zq = zc >> 2;
        float4 z = make_float4(0.f, 0.f, 0.f, 0.f);
        float* base = Pout + ((size_t)bh*SEQ + q0)*SEQ + ntiles*128;
        for (int i = tid; i < NROW * zq; i += NTHR) {
            int r = i / zq, c = (i - r * zq) * 4;
            *(float4*)(base + (size_t)r * SEQ + c) = z;
        }
    }
}

extern "C" void kernel_launch(void* const* d_in, const int* in_sizes, int n_in,
                              void* d_out, int out_size)
{
    (void)in_sizes; (void)n_in; (void)out_size;
    const float* Q   = (const float*)d_in[0];
    const float* K   = (const float*)d_in[1];
    const float* V   = (const float*)d_in[2];
    const float* PEK = (const float*)d_in[3];
    const float* PEV = (const float*)d_in[4];
    float* Out  = (float*)d_out;
    float* Pout = Out + (size_t)BH * SEQ * DH;

    convert_kernel<<<dim3(BH, 8), 256>>>(K, V);
    knorm_kernel<<<BH, 256>>>(K);
    cudaFuncSetAttribute(relattn_mma, cudaFuncAttributeMaxDynamicSharedMemorySize, SMEM_TOTAL);
    relattn_mma<<<1024, NTHR, SMEM_TOTAL>>>(Q, PEK, PEV, Out, Pout);
}

// round 10
// speedup vs baseline: 1.1294x; 1.1294x over previous
#include <cuda_runtime.h>
#include <cuda_fp16.h>
#include <math.h>
#include <stdint.h>

// B=4,H=16 -> BH=64; S=1024; D=64; rel-pos P=32
#define BH   64
#define SEQ  1024
#define DH   64
#define NTHR 256
#define NROW 64
#define ISD  0.125f
#define NEGINF (-INFINITY)

#define KW_STRW 36      // K fp16 tile stride (words)
#define VT_STRW 68      // V^T fp16 tile stride (words)
#define PST_STR 132     // p-stage stride (floats; 528B, 16B-divisible)
#define QSTG_STR 68     // fp32 Q staging stride

// smem layout (bytes)
#define OFF_K    0                       // K fp16 [128][72h]   18432   (tail: O-exchange 18432)
#define OFF_VT   18432                   // V^T fp16 [64][136h] 17408
#define OFF_PST  35840                   // p stage f32 [64][132] 33792 (preamble: Q f32 [64][68] + pe_k; tail: taps/l/inv)
#define OFF_QPE  69632                   // qpe [64][34] f32     8704
#define OFF_PEV  78336                   // pe_v [33][66] f32    8712
#define OFF_M    87048                   // M bound [64]          256
#define SMEM_TOTAL 87304

__device__ __align__(16) __half g_Kh[(size_t)BH * SEQ * DH];
__device__ __align__(16) __half g_Vth[(size_t)BH * DH * SEQ];   // [bh][d][k]
__device__ float g_maxk[BH];

static __device__ __forceinline__ uint32_t h2u(float a, float b) {
    __half2 h = __floats2half2_rn(a, b);
    return *reinterpret_cast<uint32_t*>(&h);
}
static __device__ __forceinline__ void mma16(float* d, const uint32_t* a,
                                             uint32_t b0, uint32_t b1) {
    asm volatile("mma.sync.aligned.m16n8k16.row.col.f32.f16.f16.f32 "
        "{%0,%1,%2,%3},{%4,%5,%6,%7},{%8,%9},{%0,%1,%2,%3};"
        : "+f"(d[0]), "+f"(d[1]), "+f"(d[2]), "+f"(d[3])
        : "r"(a[0]), "r"(a[1]), "r"(a[2]), "r"(a[3]), "r"(b0), "r"(b1));
}

// ---- pre-pass: K -> fp16, V -> fp16 transposed ----
__global__ __launch_bounds__(256)
void convert_kernel(const float* __restrict__ K, const float* __restrict__ V)
{
    __shared__ float ts[128][65];
    const int bh = blockIdx.x, kt = blockIdx.y, tid = threadIdx.x;
    const size_t base = (size_t)bh * SEQ * DH + (size_t)kt * 128 * DH;
    const float4* Ks = (const float4*)(K + base);
    uint2* Kd = (uint2*)(g_Kh + base);
    #pragma unroll
    for (int n = 0; n < 8; n++) {
        int i = tid + n * 256;
        float4 v = Ks[i];
        uint2 u; u.x = h2u(v.x, v.y); u.y = h2u(v.z, v.w);
        Kd[i] = u;
    }
    #pragma unroll
    for (int n = 0; n < 8; n++) {
        int i = tid + n * 256;
        int r = i >> 4, c = (i & 15) * 4;
        float4 v = *(const float4*)(V + base + r * DH + c);
        ts[r][c] = v.x; ts[r][c+1] = v.y; ts[r][c+2] = v.z; ts[r][c+3] = v.w;
    }
    __syncthreads();
    __half* Vh = g_Vth + (size_t)bh * SEQ * DH + (size_t)kt * 128;
    #pragma unroll
    for (int n = 0; n < 4; n++) {
        int i = tid + n * 256;
        int d = i >> 4, c8 = (i & 15) * 8;
        __half hv[8];
        #pragma unroll
        for (int j = 0; j < 8; j++) hv[j] = __float2half_rn(ts[c8 + j][d]);
        *(uint4*)(Vh + (size_t)d * SEQ + c8) = *(uint4*)hv;
    }
}

// ---- precompute: per-bh max ||k_row|| ----
__global__ __launch_bounds__(256, 4)
void knorm_kernel(const float* __restrict__ K)
{
    __shared__ float red[8];
    const int bh = blockIdx.x, tid = threadIdx.x;
    const float* Kb = K + (size_t)bh * SEQ * DH;
    float mx = 0.f;
    for (int r = tid; r < SEQ; r += 256) {
        const float4* kr = (const float4*)(Kb + (size_t)r * DH);
        float s = 0.f;
        #pragma unroll
        for (int i = 0; i < 16; i++) {
            float4 v = kr[i];
            s += v.x*v.x + v.y*v.y + v.z*v.z + v.w*v.w;
        }
        mx = fmaxf(mx, s);
    }
    #pragma unroll
    for (int o = 16; o > 0; o >>= 1) mx = fmaxf(mx, __shfl_xor_sync(0xffffffffu, mx, o));
    if ((tid & 31) == 0) red[tid >> 5] = mx;
    __syncthreads();
    if (tid == 0) {
        float m = red[0];
        #pragma unroll
        for (int i = 1; i < 8; i++) m = fmaxf(m, red[i]);
        g_maxk[bh] = sqrtf(m);
    }
}

__global__ __launch_bounds__(NTHR, 2)
void relattn_mma(const float* __restrict__ Q, const float* __restrict__ PEK,
                 const float* __restrict__ PEV,
                 float* __restrict__ Out, float* __restrict__ Pout)
{
    extern __shared__ char sm8[];
    uint32_t* kw  = (uint32_t*)(sm8 + OFF_K);
    uint32_t* vw  = (uint32_t*)(sm8 + OFF_VT);
    float*    sPST= (float*)(sm8 + OFF_PST);
    float*    qstg= (float*)(sm8 + OFF_PST);               // preamble overlay
    float*    sPEK= (float*)(sm8 + OFF_PST + 17408);       // preamble overlay
    float*    sQPE= (float*)(sm8 + OFF_QPE);
    float*    sPEV= (float*)(sm8 + OFF_PEV);
    float*    sM  = (float*)(sm8 + OFF_M);
    // tail overlays
    float*    sTap= (float*)(sm8 + OFF_PST);               // [64][34]
    float*    sLR = (float*)(sm8 + OFF_PST + 8704);        // [64][2]
    float*    sINV= (float*)(sm8 + OFF_PST + 9216);        // [64]
    float*    sOX = (float*)(sm8 + OFF_K);                 // O-exchange

    const int tid = threadIdx.x, lane = tid & 31, warp = tid >> 5;
    const int g = lane >> 2, tg = lane & 3;
    const int wm = warp & 3, wn = warp >> 2;               // 4 x 2 warp grid
    const int rm = wm * 16, cn = wn * 64, dn = wn * 32;

    const int bx = blockIdx.x;
    const int qblk = 15 - (bx >> 6);                       // longest first
    const int bh = bx & 63;
    const int q0 = qblk * NROW;
    const int ntiles = (q0 + NROW + 127) >> 7;

    const float* Qb = Q + (size_t)bh * SEQ * DH;
    const __half* Khb = g_Kh + (size_t)bh * SEQ * DH;
    const __half* Vthb = g_Vth + (size_t)bh * SEQ * DH;
    const float maxk = g_maxk[bh];

    // ---- preamble: stage Q fp32 + pe tables ----
    #pragma unroll
    for (int n = 0; n < 4; n++) {
        int i = tid + n * NTHR;
        int r = i >> 4, c = (i & 15) * 4;
        *(float4*)(qstg + r * QSTG_STR + c) =
            *(const float4*)(Qb + (size_t)(q0 + r) * DH + c);
    }
    for (int i = tid; i < 33 * 16; i += NTHR) {
        int r = i >> 4, c = (i & 15) * 4;
        float4 a = *(const float4*)(PEK + r * DH + c);
        sPEK[r*66+c] = a.x; sPEK[r*66+c+1] = a.y; sPEK[r*66+c+2] = a.z; sPEK[r*66+c+3] = a.w;
        float4 b = *(const float4*)(PEV + r * DH + c);
        sPEV[r*66+c] = b.x; sPEV[r*66+c+1] = b.y; sPEV[r*66+c+2] = b.z; sPEV[r*66+c+3] = b.w;
    }
    __syncthreads();

    // ---- qpe[row][j] = q_row . pe_k[j] ----
    {
        int row = tid >> 2, quarter = tid & 3;
        const float* qr = qstg + row * QSTG_STR;
        int j0 = quarter * 8, jn = (quarter == 3) ? 9 : 8;
        #pragma unroll 1
        for (int jj = 0; jj < jn; jj++) {
            int j = j0 + jj;
            const float* pk = sPEK + j * 66;
            float a = 0.f;
            #pragma unroll
            for (int d = 0; d < 64; d++) a = fmaf(qr[d], pk[d], a);
            sQPE[row * 34 + j] = a;
        }
    }
    __syncthreads();

    // ---- M bound per row; Q fragments resident ----
    if (tid < NROW) {
        const float* qr = qstg + tid * QSTG_STR;
        float qn = 0.f;
        #pragma unroll
        for (int d = 0; d < 64; d++) qn = fmaf(qr[d], qr[d], qn);
        float mb = sQPE[tid * 34];
        #pragma unroll
        for (int j = 1; j < 33; j++) mb = fmaxf(mb, sQPE[tid * 34 + j]);
        sM[tid] = sqrtf(qn) * maxk + mb;
    }
    uint32_t qa[4][4];
    #pragma unroll
    for (int ks = 0; ks < 4; ks++) {
        const float* r0 = qstg + (rm + g) * QSTG_STR + 16*ks + 2*tg;
        const float* r1 = qstg + (rm + 8 + g) * QSTG_STR + 16*ks + 2*tg;
        qa[ks][0] = h2u(r0[0], r0[1]);
        qa[ks][1] = h2u(r1[0], r1[1]);
        qa[ks][2] = h2u(r0[8], r0[9]);
        qa[ks][3] = h2u(r1[8], r1[9]);
    }
    __syncthreads();

    float Mrow[2];
    #pragma unroll
    for (int s = 0; s < 2; s++) Mrow[s] = sM[rm + 8*s + g];

    // ================= main loop =================
    float lc[4] = {0.f, 0.f, 0.f, 0.f};   // per-c partial row sums
    float o[8][4] = {};

    for (int kt = 0; kt < ntiles; kt++) {
        // register prefetch of fp16 K/V (overlaps previous tile's PV + barrier)
        uint4 kpre[4], vpre[4];
        #pragma unroll
        for (int n = 0; n < 4; n++) {
            int idx = tid + n * NTHR;
            int r = idx >> 3, c8 = (idx & 7) * 8;
            kpre[n] = *(const uint4*)(Khb + (size_t)(kt * 128 + r) * DH + c8);
        }
        #pragma unroll
        for (int n = 0; n < 4; n++) {
            int idx = tid + n * NTHR;
            int d = idx >> 4, c8 = (idx & 15) * 8;
            vpre[n] = *(const uint4*)(Vthb + (size_t)d * SEQ + kt * 128 + c8);
        }
        __syncthreads();   // A: prev tile's smem reads + p-stage writes complete

        #pragma unroll
        for (int n = 0; n < 4; n++) {
            int idx = tid + n * NTHR;
            int r = idx >> 3;
            *(uint4*)(kw + r * KW_STRW + (idx & 7) * 4) = kpre[n];
        }
        #pragma unroll
        for (int n = 0; n < 4; n++) {
            int idx = tid + n * NTHR;
            int d = idx >> 4;
            *(uint4*)(vw + d * VT_STRW + (idx & 15) * 4) = vpre[n];
        }
        // stream out previous tile's p-stage (coalesced)
        if (kt > 0) {
            int ct = (kt - 1) * 128;
            #pragma unroll
            for (int j = 0; j < 8; j++) {
                int r = warp * 8 + j;
                float4 v = *(const float4*)(sPST + r * PST_STR + 4 * lane);
                *(float4*)(Pout + ((size_t)bh*SEQ + q0 + r)*SEQ + ct + 4*lane) = v;
            }
        }
        __syncthreads();   // B: tile staged, stream-out done

        const bool live = (kt*128 + cn) <= (q0 + rm + 15);

        if (live) {
            // ---- score: 16 rows x 64 cols ----
            float acc[8][4] = {};
            #pragma unroll
            for (int ks = 0; ks < 4; ks++)
                #pragma unroll
                for (int nt = 0; nt < 8; nt++) {
                    int bb = (cn + 8*nt + g) * KW_STRW + 8*ks + tg;
                    mma16(acc[nt], qa[ks], kw[bb], kw[bb + 4]);
                }

            // ---- bias + mask + e; STS p-stage; pack PV A-frags ----
            uint32_t pa[4][4];
            #pragma unroll
            for (int nt = 0; nt < 8; nt++) {
                float p[4];
                #pragma unroll
                for (int c = 0; c < 4; c++) {
                    int s = c >> 1;
                    int row = rm + 8*s + g;
                    int col = kt*128 + cn + 8*nt + 2*tg + (c&1);
                    int qg = q0 + row;
                    float v = NEGINF;
                    if (col <= qg) {
                        int j = col - qg + 32; j = j < 0 ? 0 : j;
                        v = acc[nt][c] + sQPE[row*34 + j];
                    }
                    float e = __expf((v - Mrow[s]) * ISD);
                    p[c] = e;
                    lc[c] += e;
                }
                int cl = cn + 8*nt + 2*tg;
                *(float2*)(sPST + (rm + g) * PST_STR + cl)     = make_float2(p[0], p[1]);
                *(float2*)(sPST + (rm + 8 + g) * PST_STR + cl) = make_float2(p[2], p[3]);
                int ki = nt >> 1;
                if ((nt & 1) == 0) { pa[ki][0] = h2u(p[0], p[1]); pa[ki][1] = h2u(p[2], p[3]); }
                else               { pa[ki][2] = h2u(p[0], p[1]); pa[ki][3] = h2u(p[2], p[3]); }
            }

            // ---- PV from registers over this warp's 64 keys ----
            #pragma unroll
            for (int ks = 0; ks < 4; ks++) {
                if (kt*128 + cn + 16*ks <= q0 + rm + 15) {
                    #pragma unroll
                    for (int nt = 0; nt < 8; nt++) {
                        int bb = (8*nt + g) * VT_STRW + (cn >> 1) + 8*ks + tg;
                        mma16(o[nt], pa[ks], vw[bb], vw[bb + 4]);
                    }
                }
            }
        } else {
            float2 z = make_float2(0.f, 0.f);
            #pragma unroll
            for (int nt = 0; nt < 8; nt++) {
                int cl = cn + 8*nt + 2*tg;
                *(float2*)(sPST + (rm + g) * PST_STR + cl)     = z;
                *(float2*)(sPST + (rm + 8 + g) * PST_STR + cl) = z;
            }
        }
    }
    __syncthreads();   // all p-stage writes for last tile complete

    // ---- stream out final tile ----
    {
        int ct = (ntiles - 1) * 128;
        #pragma unroll
        for (int j = 0; j < 8; j++) {
            int r = warp * 8 + j;
            float4 v = *(const float4*)(sPST + r * PST_STR + 4 * lane);
            *(float4*)(Pout + ((size_t)bh*SEQ + q0 + r)*SEQ + ct + 4*lane) = v;
        }
    }
    // fold l partials, warp-level reduce
    float lloc[2] = { lc[0] + lc[1], lc[2] + lc[3] };
    #pragma unroll
    for (int s = 0; s < 2; s++) {
        lloc[s] += __shfl_xor_sync(0xffffffffu, lloc[s], 1);
        lloc[s] += __shfl_xor_sync(0xffffffffu, lloc[s], 2);
    }
    __syncthreads();   // stream-out visible; p-stage free for overlays

    // ---- taps from Pout (L2-hot), l partials, O-exchange ----
    {
        int row = tid >> 2, part = tid & 3;
        int qg = q0 + row;
        const float* Prow = Pout + ((size_t)bh*SEQ + qg)*SEQ;
        #pragma unroll
        for (int i = 0; i < 8; i++) {
            int j = part*8 + 1 + i;
            int col = qg - 32 + j;
            sTap[row*34 + j] = (col >= 0) ? Prow[col] : 0.f;
        }
    }
    if (tg == 0)
        #pragma unroll
        for (int s = 0; s < 2; s++)
            sLR[(rm + 8*s + g)*2 + wn] = lloc[s];
    {
        float* dst = sOX + wn*2304 + wm*576;
        #pragma unroll
        for (int j = 0; j < 4; j++) {
            int nt = 4*(1 - wn) + j;
            dst[g*36 + 8*j + 2*tg]         = o[nt][0];
            dst[g*36 + 8*j + 2*tg + 1]     = o[nt][1];
            dst[(g+8)*36 + 8*j + 2*tg]     = o[nt][2];
            dst[(g+8)*36 + 8*j + 2*tg + 1] = o[nt][3];
        }
    }
    __syncthreads();

    // ---- per-row l, w0 = l - sum(taps), inv ----
    if (tid < NROW) {
        float l = sLR[tid*2] + sLR[tid*2+1];
        float sum = 0.f;
        #pragma unroll
        for (int j = 1; j <= 32; j++) sum += sTap[tid*34 + j];
        sINV[tid] = 1.f / l;
        sTap[tid*34] = l - sum;   // raw w0
    }
    __syncthreads();

    // ---- combine O halves, normalize, rel-pos value epilogue ----
    float oo[4][4];
    {
        const float* src = sOX + (1 - wn)*2304 + wm*576;
        #pragma unroll
        for (int j = 0; j < 4; j++) {
            int nt = 4*wn + j;
            oo[j][0] = o[nt][0] + src[g*36 + 8*j + 2*tg];
            oo[j][1] = o[nt][1] + src[g*36 + 8*j + 2*tg + 1];
            oo[j][2] = o[nt][2] + src[(g+8)*36 + 8*j + 2*tg];
            oo[j][3] = o[nt][3] + src[(g+8)*36 + 8*j + 2*tg + 1];
        }
    }
    float invl[2] = { sINV[rm + g], sINV[rm + 8 + g] };
    #pragma unroll
    for (int nt = 0; nt < 4; nt++)
        #pragma unroll
        for (int c = 0; c < 4; c++)
            oo[nt][c] *= invl[c>>1];

    #pragma unroll 1
    for (int j = 0; j <= 32; j++) {
        float wj0 = sTap[(rm + g)*34 + j] * invl[0];
        float wj1 = sTap[(rm + 8 + g)*34 + j] * invl[1];
        #pragma unroll
        for (int nt = 0; nt < 4; nt++) {
            float pe0 = sPEV[j*66 + dn + 8*nt + 2*tg];
            float pe1 = sPEV[j*66 + dn + 8*nt + 2*tg + 1];
            oo[nt][0] = fmaf(wj0, pe0, oo[nt][0]);
            oo[nt][1] = fmaf(wj0, pe1, oo[nt][1]);
            oo[nt][2] = fmaf(wj1, pe0, oo[nt][2]);
            oo[nt][3] = fmaf(wj1, pe1, oo[nt][3]);
        }
    }

    // ---- write output ----
    #pragma unroll
    for (int nt = 0; nt < 4; nt++) {
        int rowL = rm + g, rowH = rm + 8 + g;
        int colb = dn + 8*nt + 2*tg;
        *(float2*)(Out + ((size_t)bh*SEQ + q0 + rowL)*DH + colb) = make_float2(oo[nt][0], oo[nt][1]);
        *(float2*)(Out + ((size_t)bh*SEQ + q0 + rowH)*DH + colb) = make_float2(oo[nt][2], oo[nt][3]);
    }

    // ---- in-place rescale of Pout (e -> p = e/l), L2-hot ----
    {
        const int cols = ntiles * 128;
        for (int r = warp; r < NROW; r += 8) {
            float inv = sINV[r];
            float4* rowp = (float4*)(Pout + ((size_t)bh*SEQ + q0 + r)*SEQ);
            for (int c4 = lane; c4 < (cols >> 2); c4 += 32) {
                float4 v = rowp[c4];
                v.x *= inv; v.y *= inv; v.z *= inv; v.w *= inv;
                rowp[c4] = v;
            }
        }
    }

    // ---- zero-fill masked p region ----
    int zc = SEQ - ntiles * 128;
    if (zc > 0) {
        int zq = zc >> 2;
        float4 z = make_float4(0.f, 0.f, 0.f, 0.f);
        float* base = Pout + ((size_t)bh*SEQ + q0)*SEQ + ntiles*128;
        for (int i = tid; i < NROW * zq; i += NTHR) {
            int r = i / zq, c = (i - r * zq) * 4;
            *(float4*)(base + (size_t)r * SEQ + c) = z;
        }
    }
}

extern "C" void kernel_launch(void* const* d_in, const int* in_sizes, int n_in,
                              void* d_out, int out_size)
{
    (void)in_sizes; (void)n_in; (void)out_size;
    const float* Q   = (const float*)d_in[0];
    const float* K   = (const float*)d_in[1];
    const float* V   = (const float*)d_in[2];
    const float* PEK = (const float*)d_in[3];
    const float* PEV = (const float*)d_in[4];
    float* Out  = (float*)d_out;
    float* Pout = Out + (size_t)BH * SEQ * DH;

    convert_kernel<<<dim3(BH, 8), 256>>>(K, V);
    knorm_kernel<<<BH, 256>>>(K);
    cudaFuncSetAttribute(relattn_mma, cudaFuncAttributeMaxDynamicSharedMemorySize, SMEM_TOTAL);
    relattn_mma<<<1024, NTHR, SMEM_TOTAL>>>(Q, PEK, PEV, Out, Pout);
}

// round 11
// speedup vs baseline: 1.2145x; 1.0754x over previous
#include <cuda_runtime.h>
#include <cuda_fp16.h>
#include <math.h>
#include <stdint.h>

// B=4,H=16 -> BH=64; S=1024; D=64; rel-pos P=32
#define BH   64
#define SEQ  1024
#define DH   64
#define NTHR 256
#define NROW 64
#define ISD  0.125f
#define NEGINF (-INFINITY)

#define KW_STRW 36      // K fp16 tile stride (words)
#define VT_STRW 68      // V^T fp16 tile stride (words)
#define PST_STR 132     // p-stage stride (floats; 528B, 16B-divisible)
#define QSTG_STR 68     // fp32 Q staging stride

// smem layout (bytes)
#define OFF_K    0                       // K fp16 [128][72h]   18432   (tail: O-exchange)
#define OFF_VT   18432                   // V^T fp16 [64][136h] 17408
#define OFF_PST  35840                   // p stage f32 [64][132] 33792 (preamble: Q f32 + pe_k; tail: taps/l/inv)
#define OFF_QPE  69632                   // qpe [64][34] f32     8704
#define OFF_PEV  78336                   // pe_v [33][66] f32    8712
#define OFF_M    87048                   // M bound [64]          256
#define SMEM_TOTAL 87304

__device__ __align__(16) __half g_Kh[(size_t)BH * SEQ * DH];
__device__ __align__(16) __half g_Vth[(size_t)BH * DH * SEQ];   // [bh][d][k]
__device__ unsigned int g_maxkq[BH];    // max ||k_row||^2 as float bits (atomicMax, idempotent)

static __device__ __forceinline__ uint32_t h2u(float a, float b) {
    __half2 h = __floats2half2_rn(a, b);
    return *reinterpret_cast<uint32_t*>(&h);
}
static __device__ __forceinline__ void mma16(float* d, const uint32_t* a,
                                             uint32_t b0, uint32_t b1) {
    asm volatile("mma.sync.aligned.m16n8k16.row.col.f32.f16.f16.f32 "
        "{%0,%1,%2,%3},{%4,%5,%6,%7},{%8,%9},{%0,%1,%2,%3};"
        : "+f"(d[0]), "+f"(d[1]), "+f"(d[2]), "+f"(d[3])
        : "r"(a[0]), "r"(a[1]), "r"(a[2]), "r"(a[3]), "r"(b0), "r"(b1));
}

// ---- pre-pass: K -> fp16 (+ fused row-norm max), V -> fp16 transposed ----
__global__ __launch_bounds__(512)
void convert_kernel(const float* __restrict__ K, const float* __restrict__ V)
{
    __shared__ float ts[128][65];
    const int bh = blockIdx.x, kt = blockIdx.y, tid = threadIdx.x;
    const int lane = tid & 31;
    const size_t base = (size_t)bh * SEQ * DH + (size_t)kt * 128 * DH;

    // K: convert + per-row ||k||^2 (16 lanes per row), track block max
    const float4* Ks = (const float4*)(K + base);
    uint2* Kd = (uint2*)(g_Kh + base);
    float mxq = 0.f;
    #pragma unroll
    for (int n = 0; n < 4; n++) {
        int i = tid + n * 512;
        float4 v = Ks[i];
        uint2 u; u.x = h2u(v.x, v.y); u.y = h2u(v.z, v.w);
        Kd[i] = u;
        float sq = v.x*v.x + v.y*v.y + v.z*v.z + v.w*v.w;
        #pragma unroll
        for (int o = 1; o <= 8; o <<= 1) sq += __shfl_xor_sync(0xffffffffu, sq, o);
        mxq = fmaxf(mxq, sq);
    }
    #pragma unroll
    for (int o = 16; o >= 1; o >>= 1) mxq = fmaxf(mxq, __shfl_xor_sync(0xffffffffu, mxq, o));
    if (lane == 0) atomicMax(&g_maxkq[bh], __float_as_uint(mxq));

    // V: transpose via smem, fp16 out
    #pragma unroll
    for (int n = 0; n < 4; n++) {
        int i = tid + n * 512;
        int r = i >> 4, c = (i & 15) * 4;
        float4 v = *(const float4*)(V + base + r * DH + c);
        ts[r][c] = v.x; ts[r][c+1] = v.y; ts[r][c+2] = v.z; ts[r][c+3] = v.w;
    }
    __syncthreads();
    __half* Vh = g_Vth + (size_t)bh * SEQ * DH + (size_t)kt * 128;
    #pragma unroll
    for (int n = 0; n < 2; n++) {
        int i = tid + n * 512;
        int d = i >> 4, c8 = (i & 15) * 8;
        __half hv[8];
        #pragma unroll
        for (int j = 0; j < 8; j++) hv[j] = __float2half_rn(ts[c8 + j][d]);
        *(uint4*)(Vh + (size_t)d * SEQ + c8) = *(uint4*)hv;
    }
}

__global__ __launch_bounds__(NTHR, 2)
void relattn_mma(const float* __restrict__ Q, const float* __restrict__ PEK,
                 const float* __restrict__ PEV,
                 float* __restrict__ Out, float* __restrict__ Pout)
{
    extern __shared__ char sm8[];
    uint32_t* kw  = (uint32_t*)(sm8 + OFF_K);
    uint32_t* vw  = (uint32_t*)(sm8 + OFF_VT);
    float*    sPST= (float*)(sm8 + OFF_PST);
    float*    qstg= (float*)(sm8 + OFF_PST);               // preamble overlay
    float*    sPEK= (float*)(sm8 + OFF_PST + 17408);       // preamble overlay
    float*    sQPE= (float*)(sm8 + OFF_QPE);
    float*    sPEV= (float*)(sm8 + OFF_PEV);
    float*    sM  = (float*)(sm8 + OFF_M);
    // tail overlays
    float*    sTap= (float*)(sm8 + OFF_PST);               // [64][34]
    float*    sLR = (float*)(sm8 + OFF_PST + 8704);        // [64][2]
    float*    sINV= (float*)(sm8 + OFF_PST + 9216);        // [64]
    float*    sOX = (float*)(sm8 + OFF_K);                 // O-exchange

    const int tid = threadIdx.x, lane = tid & 31, warp = tid >> 5;
    const int g = lane >> 2, tg = lane & 3;
    const int wm = warp & 3, wn = warp >> 2;               // 4 x 2 warp grid
    const int rm = wm * 16, cn = wn * 64, dn = wn * 32;

    const int bx = blockIdx.x;
    const int qblk = 15 - (bx >> 6);                       // longest first
    const int bh = bx & 63;
    const int q0 = qblk * NROW;
    const int ntiles = (q0 + NROW + 127) >> 7;

    const float* Qb = Q + (size_t)bh * SEQ * DH;
    const __half* Khb = g_Kh + (size_t)bh * SEQ * DH;
    const __half* Vthb = g_Vth + (size_t)bh * SEQ * DH;
    const float maxk = sqrtf(__uint_as_float(g_maxkq[bh]));

    // ---- preamble: stage Q fp32 + pe tables ----
    #pragma unroll
    for (int n = 0; n < 4; n++) {
        int i = tid + n * NTHR;
        int r = i >> 4, c = (i & 15) * 4;
        *(float4*)(qstg + r * QSTG_STR + c) =
            *(const float4*)(Qb + (size_t)(q0 + r) * DH + c);
    }
    for (int i = tid; i < 33 * 16; i += NTHR) {
        int r = i >> 4, c = (i & 15) * 4;
        float4 a = *(const float4*)(PEK + r * DH + c);
        sPEK[r*66+c] = a.x; sPEK[r*66+c+1] = a.y; sPEK[r*66+c+2] = a.z; sPEK[r*66+c+3] = a.w;
        float4 b = *(const float4*)(PEV + r * DH + c);
        sPEV[r*66+c] = b.x; sPEV[r*66+c+1] = b.y; sPEV[r*66+c+2] = b.z; sPEV[r*66+c+3] = b.w;
    }
    __syncthreads();

    // ---- qpe[row][j] = q_row . pe_k[j] ----
    {
        int row = tid >> 2, quarter = tid & 3;
        const float* qr = qstg + row * QSTG_STR;
        int j0 = quarter * 8, jn = (quarter == 3) ? 9 : 8;
        #pragma unroll 1
        for (int jj = 0; jj < jn; jj++) {
            int j = j0 + jj;
            const float* pk = sPEK + j * 66;
            float a = 0.f;
            #pragma unroll
            for (int d = 0; d < 64; d++) a = fmaf(qr[d], pk[d], a);
            sQPE[row * 34 + j] = a;
        }
    }
    __syncthreads();

    // ---- M bound per row; Q fragments resident ----
    if (tid < NROW) {
        const float* qr = qstg + tid * QSTG_STR;
        float qn = 0.f;
        #pragma unroll
        for (int d = 0; d < 64; d++) qn = fmaf(qr[d], qr[d], qn);
        float mb = sQPE[tid * 34];
        #pragma unroll
        for (int j = 1; j < 33; j++) mb = fmaxf(mb, sQPE[tid * 34 + j]);
        sM[tid] = sqrtf(qn) * maxk + mb;
    }
    uint32_t qa[4][4];
    #pragma unroll
    for (int ks = 0; ks < 4; ks++) {
        const float* r0 = qstg + (rm + g) * QSTG_STR + 16*ks + 2*tg;
        const float* r1 = qstg + (rm + 8 + g) * QSTG_STR + 16*ks + 2*tg;
        qa[ks][0] = h2u(r0[0], r0[1]);
        qa[ks][1] = h2u(r1[0], r1[1]);
        qa[ks][2] = h2u(r0[8], r0[9]);
        qa[ks][3] = h2u(r1[8], r1[9]);
    }
    __syncthreads();

    float Mrow[2];
    #pragma unroll
    for (int s = 0; s < 2; s++) Mrow[s] = sM[rm + 8*s + g];

    // ================= main loop =================
    float lc[4] = {0.f, 0.f, 0.f, 0.f};
    float o[8][4] = {};

    for (int kt = 0; kt < ntiles; kt++) {
        // register prefetch of fp16 K/V (overlaps previous tile's PV + barrier)
        uint4 kpre[4], vpre[4];
        #pragma unroll
        for (int n = 0; n < 4; n++) {
            int idx = tid + n * NTHR;
            int r = idx >> 3, c8 = (idx & 7) * 8;
            kpre[n] = *(const uint4*)(Khb + (size_t)(kt * 128 + r) * DH + c8);
        }
        #pragma unroll
        for (int n = 0; n < 4; n++) {
            int idx = tid + n * NTHR;
            int d = idx >> 4, c8 = (idx & 15) * 8;
            vpre[n] = *(const uint4*)(Vthb + (size_t)d * SEQ + kt * 128 + c8);
        }
        __syncthreads();   // A: prev tile's smem reads + p-stage writes complete

        #pragma unroll
        for (int n = 0; n < 4; n++) {
            int idx = tid + n * NTHR;
            int r = idx >> 3;
            *(uint4*)(kw + r * KW_STRW + (idx & 7) * 4) = kpre[n];
        }
        #pragma unroll
        for (int n = 0; n < 4; n++) {
            int idx = tid + n * NTHR;
            int d = idx >> 4;
            *(uint4*)(vw + d * VT_STRW + (idx & 15) * 4) = vpre[n];
        }
        // stream out previous tile's p-stage (coalesced)
        if (kt > 0) {
            int ct = (kt - 1) * 128;
            #pragma unroll
            for (int j = 0; j < 8; j++) {
                int r = warp * 8 + j;
                float4 v = *(const float4*)(sPST + r * PST_STR + 4 * lane);
                *(float4*)(Pout + ((size_t)bh*SEQ + q0 + r)*SEQ + ct + 4*lane) = v;
            }
        }
        __syncthreads();   // B: tile staged, stream-out done

        const bool live = (kt*128 + cn) <= (q0 + rm + 15);

        if (live) {
            const int ntmax = min(8, ((q0 + rm + 15 - kt*128 - cn) >> 3) + 1);
            const bool far = (kt*128 + cn + 63) <= (q0 + rm - 32);

            // ---- score: 16 rows x (8*ntmax) cols ----
            float acc[8][4] = {};
            #pragma unroll
            for (int ks = 0; ks < 4; ks++)
                #pragma unroll
                for (int nt = 0; nt < 8; nt++)
                    if (nt < ntmax) {
                        int bb = (cn + 8*nt + g) * KW_STRW + 8*ks + tg;
                        mma16(acc[nt], qa[ks], kw[bb], kw[bb + 4]);
                    }

            uint32_t pa[4][4] = {};
            if (far) {
                // entire slice below rel-pos band: j==0, nothing masked
                float b0 = (sQPE[(rm + g) * 34]     - Mrow[0]) * ISD;
                float b1 = (sQPE[(rm + 8 + g) * 34] - Mrow[1]) * ISD;
                #pragma unroll
                for (int nt = 0; nt < 8; nt++) {
                    float p[4];
                    p[0] = __expf(fmaf(acc[nt][0], ISD, b0));
                    p[1] = __expf(fmaf(acc[nt][1], ISD, b0));
                    p[2] = __expf(fmaf(acc[nt][2], ISD, b1));
                    p[3] = __expf(fmaf(acc[nt][3], ISD, b1));
                    lc[0] += p[0]; lc[1] += p[1]; lc[2] += p[2]; lc[3] += p[3];
                    int cl = cn + 8*nt + 2*tg;
                    *(float2*)(sPST + (rm + g) * PST_STR + cl)     = make_float2(p[0], p[1]);
                    *(float2*)(sPST + (rm + 8 + g) * PST_STR + cl) = make_float2(p[2], p[3]);
                    int ki = nt >> 1;
                    if ((nt & 1) == 0) { pa[ki][0] = h2u(p[0], p[1]); pa[ki][1] = h2u(p[2], p[3]); }
                    else               { pa[ki][2] = h2u(p[0], p[1]); pa[ki][3] = h2u(p[2], p[3]); }
                }
            } else {
                #pragma unroll
                for (int nt = 0; nt < 8; nt++) {
                    if (nt < ntmax) {
                        float p[4];
                        #pragma unroll
                        for (int c = 0; c < 4; c++) {
                            int s = c >> 1;
                            int row = rm + 8*s + g;
                            int col = kt*128 + cn + 8*nt + 2*tg + (c&1);
                            int qg = q0 + row;
                            float v = NEGINF;
                            if (col <= qg) {
                                int j = col - qg + 32; j = j < 0 ? 0 : j;
                                v = acc[nt][c] + sQPE[row*34 + j];
                            }
                            float e = __expf((v - Mrow[s]) * ISD);
                            p[c] = e;
                            lc[c] += e;
                        }
                        int cl = cn + 8*nt + 2*tg;
                        *(float2*)(sPST + (rm + g) * PST_STR + cl)     = make_float2(p[0], p[1]);
                        *(float2*)(sPST + (rm + 8 + g) * PST_STR + cl) = make_float2(p[2], p[3]);
                        int ki = nt >> 1;
                        if ((nt & 1) == 0) { pa[ki][0] = h2u(p[0], p[1]); pa[ki][1] = h2u(p[2], p[3]); }
                        else               { pa[ki][2] = h2u(p[0], p[1]); pa[ki][3] = h2u(p[2], p[3]); }
                    } else {
                        float2 z = make_float2(0.f, 0.f);
                        int cl = cn + 8*nt + 2*tg;
                        *(float2*)(sPST + (rm + g) * PST_STR + cl)     = z;
                        *(float2*)(sPST + (rm + 8 + g) * PST_STR + cl) = z;
                    }
                }
            }

            // ---- PV from registers over this warp's 64 keys ----
            #pragma unroll
            for (int ks = 0; ks < 4; ks++) {
                if (kt*128 + cn + 16*ks <= q0 + rm + 15) {
                    #pragma unroll
                    for (int nt = 0; nt < 8; nt++) {
                        int bb = (8*nt + g) * VT_STRW + (cn >> 1) + 8*ks + tg;
                        mma16(o[nt], pa[ks], vw[bb], vw[bb + 4]);
                    }
                }
            }
        } else {
            float2 z = make_float2(0.f, 0.f);
            #pragma unroll
            for (int nt = 0; nt < 8; nt++) {
                int cl = cn + 8*nt + 2*tg;
                *(float2*)(sPST + (rm + g) * PST_STR + cl)     = z;
                *(float2*)(sPST + (rm + 8 + g) * PST_STR + cl) = z;
            }
        }
    }
    __syncthreads();   // all p-stage writes for last tile complete

    // ---- stream out final tile ----
    {
        int ct = (ntiles - 1) * 128;
        #pragma unroll
        for (int j = 0; j < 8; j++) {
            int r = warp * 8 + j;
            float4 v = *(const float4*)(sPST + r * PST_STR + 4 * lane);
            *(float4*)(Pout + ((size_t)bh*SEQ + q0 + r)*SEQ + ct + 4*lane) = v;
        }
    }
    float lloc[2] = { lc[0] + lc[1], lc[2] + lc[3] };
    #pragma unroll
    for (int s = 0; s < 2; s++) {
        lloc[s] += __shfl_xor_sync(0xffffffffu, lloc[s], 1);
        lloc[s] += __shfl_xor_sync(0xffffffffu, lloc[s], 2);
    }
    __syncthreads();   // stream-out visible; p-stage free for overlays

    // ---- taps from Pout (L2-hot), l partials, O-exchange ----
    {
        int row = tid >> 2, part = tid & 3;
        int qg = q0 + row;
        const float* Prow = Pout + ((size_t)bh*SEQ + qg)*SEQ;
        #pragma unroll
        for (int i = 0; i < 8; i++) {
            int j = part*8 + 1 + i;
            int col = qg - 32 + j;
            sTap[row*34 + j] = (col >= 0) ? Prow[col] : 0.f;
        }
    }
    if (tg == 0)
        #pragma unroll
        for (int s = 0; s < 2; s++)
            sLR[(rm + 8*s + g)*2 + wn] = lloc[s];
    {
        float* dst = sOX + wn*2304 + wm*576;
        #pragma unroll
        for (int j = 0; j < 4; j++) {
            int nt = 4*(1 - wn) + j;
            dst[g*36 + 8*j + 2*tg]         = o[nt][0];
            dst[g*36 + 8*j + 2*tg + 1]     = o[nt][1];
            dst[(g+8)*36 + 8*j + 2*tg]     = o[nt][2];
            dst[(g+8)*36 + 8*j + 2*tg + 1] = o[nt][3];
        }
    }
    __syncthreads();

    // ---- per-row l, w0 = l - sum(taps), inv ----
    if (tid < NROW) {
        float l = sLR[tid*2] + sLR[tid*2+1];
        float sum = 0.f;
        #pragma unroll
        for (int j = 1; j <= 32; j++) sum += sTap[tid*34 + j];
        sINV[tid] = 1.f / l;
        sTap[tid*34] = l - sum;   // raw w0
    }
    __syncthreads();

    // ---- combine O halves, normalize, rel-pos value epilogue ----
    float oo[4][4];
    {
        const float* src = sOX + (1 - wn)*2304 + wm*576;
        #pragma unroll
        for (int j = 0; j < 4; j++) {
            int nt = 4*wn + j;
            oo[j][0] = o[nt][0] + src[g*36 + 8*j + 2*tg];
            oo[j][1] = o[nt][1] + src[g*36 + 8*j + 2*tg + 1];
            oo[j][2] = o[nt][2] + src[(g+8)*36 + 8*j + 2*tg];
            oo[j][3] = o[nt][3] + src[(g+8)*36 + 8*j + 2*tg + 1];
        }
    }
    float invl[2] = { sINV[rm + g], sINV[rm + 8 + g] };
    #pragma unroll
    for (int nt = 0; nt < 4; nt++)
        #pragma unroll
        for (int c = 0; c < 4; c++)
            oo[nt][c] *= invl[c>>1];

    #pragma unroll 1
    for (int j = 0; j <= 32; j++) {
        float wj0 = sTap[(rm + g)*34 + j] * invl[0];
        float wj1 = sTap[(rm + 8 + g)*34 + j] * invl[1];
        #pragma unroll
        for (int nt = 0; nt < 4; nt++) {
            float pe0 = sPEV[j*66 + dn + 8*nt + 2*tg];
            float pe1 = sPEV[j*66 + dn + 8*nt + 2*tg + 1];
            oo[nt][0] = fmaf(wj0, pe0, oo[nt][0]);
            oo[nt][1] = fmaf(wj0, pe1, oo[nt][1]);
            oo[nt][2] = fmaf(wj1, pe0, oo[nt][2]);
            oo[nt][3] = fmaf(wj1, pe1, oo[nt][3]);
        }
    }

    // ---- write output ----
    #pragma unroll
    for (int nt = 0; nt < 4; nt++) {
        int rowL = rm + g, rowH = rm + 8 + g;
        int colb = dn + 8*nt + 2*tg;
        *(float2*)(Out + ((size_t)bh*SEQ + q0 + rowL)*DH + colb) = make_float2(oo[nt][0], oo[nt][1]);
        *(float2*)(Out + ((size_t)bh*SEQ + q0 + rowH)*DH + colb) = make_float2(oo[nt][2], oo[nt][3]);
    }

    // ---- in-place rescale of Pout (e -> p = e/l), L2-hot ----
    {
        const int cols = ntiles * 128;
        for (int r = warp; r < NROW; r += 8) {
            float inv = sINV[r];
            float4* rowp = (float4*)(Pout + ((size_t)bh*SEQ + q0 + r)*SEQ);
            for (int c4 = lane; c4 < (cols >> 2); c4 += 32) {
                float4 v = rowp[c4];
                v.x *= inv; v.y *= inv; v.z *= inv; v.w *= inv;
                rowp[c4] = v;
            }
        }
    }

    // ---- zero-fill masked p region ----
    int zc = SEQ - ntiles * 128;
    if (zc > 0) {
        int zq = zc >> 2;
        float4 z = make_float4(0.f, 0.f, 0.f, 0.f);
        float* base = Pout + ((size_t)bh*SEQ + q0)*SEQ + ntiles*128;
        for (int i = tid; i < NROW * zq; i += NTHR) {
            int r = i / zq, c = (i - r * zq) * 4;
            *(float4*)(base + (size_t)r * SEQ + c) = z;
        }
    }
}

extern "C" void kernel_launch(void* const* d_in, const int* in_sizes, int n_in,
                              void* d_out, int out_size)
{
    (void)in_sizes; (void)n_in; (void)out_size;
    const float* Q   = (const float*)d_in[0];
    const float* K   = (const float*)d_in[1];
    const float* V   = (const float*)d_in[2];
    const float* PEK = (const float*)d_in[3];
    const float* PEV = (const float*)d_in[4];
    float* Out  = (float*)d_out;
    float* Pout = Out + (size_t)BH * SEQ * DH;

    convert_kernel<<<dim3(BH, 8), 512>>>(K, V);
    cudaFuncSetAttribute(relattn_mma, cudaFuncAttributeMaxDynamicSharedMemorySize, SMEM_TOTAL);
    relattn_mma<<<1024, NTHR, SMEM_TOTAL>>>(Q, PEK, PEV, Out, Pout);
}